// round 11
// baseline (speedup 1.0000x reference)
#include <cuda_runtime.h>

#define THREADS 256
#define NWARP (THREADS / 32)
#define TOPK 5
#define NCAT 8
#define CAP 512
#define FULLM 0xffffffffu
#define L2E 1.4426950408889634f
#define LN2 0.6931471805599453f
#define NEG_INF (-__int_as_float(0x7f800000))
#define THRESH 3.25f

__device__ float g_rowloss[8192];
__device__ unsigned int g_done = 0;

__device__ __forceinline__ float ex2f(float x) {
    float y; asm("ex2.approx.ftz.f32 %0, %1;" : "=f"(y) : "f"(x)); return y;
}
__device__ __forceinline__ float lg2f(float x) {
    float y; asm("lg2.approx.ftz.f32 %0, %1;" : "=f"(y) : "f"(x)); return y;
}

__device__ __forceinline__ void insert5(float (&tv)[TOPK], int (&ti)[TOPK], float v, int idx) {
    tv[TOPK - 1] = v; ti[TOPK - 1] = idx;
#pragma unroll
    for (int k = TOPK - 1; k > 0; --k) {
        if (tv[k] > tv[k - 1]) {
            float tf = tv[k]; tv[k] = tv[k - 1]; tv[k - 1] = tf;
            int   tt = ti[k]; ti[k] = ti[k - 1]; ti[k - 1] = tt;
        }
    }
}

__global__ void __launch_bounds__(THREADS, 8)
hier_loss_fused(const float* __restrict__ logits,
                const int* __restrict__ labels,
                const int* __restrict__ catlab,
                const int* __restrict__ c2c,
                float* __restrict__ out,
                int V, int ncmd, int B)
{
    const int b   = blockIdx.x;
    const int tid = threadIdx.x;
    const float* row = logits + (size_t)b * (size_t)V;

    __shared__ int   s_c2c[64];
    __shared__ float s_wS[NWARP];
    __shared__ float s_vals[CAP];
    __shared__ int   s_idx[CAP];
    __shared__ int   s_cnt;
    __shared__ float s_cat[NCAT];
    __shared__ int   s_isLast;
    __shared__ float s_red[THREADS];

    if (tid < 64 && tid < ncmd) s_c2c[tid] = c2c[tid];
    if (tid == 0) s_cnt = 0;
    __syncthreads();

    const float negC = -__ldg(row) * L2E;      // block-wide base (log2 domain)
    float s0 = 0.f, s1 = 0.f;

    const int mis = (int)(((size_t)b * (size_t)V) & 3);
    const int pre = (4 - mis) & 3;
    const int nv4 = (V - pre) >> 2;
    const int nIter2 = nv4 / (2 * THREADS);    // 2 x float4 per thread per step
    const int vecElems = nIter2 * 8 * THREADS;
    const float4* __restrict__ p4base = (const float4*)(row + pre);
    const float4* __restrict__ p4 = p4base + tid;

#define PUSH(val, ei)                                                         \
    do {                                                                      \
        if ((val) > THRESH) {                                                 \
            int pos = atomicAdd(&s_cnt, 1);                                   \
            if (pos < CAP) { s_vals[pos] = (val); s_idx[pos] = (ei); }        \
        }                                                                     \
    } while (0)

    // ---- head (pre <= 3 elements) ----
    if (tid < pre) {
        float x = __ldg(row + tid);
        s0 += ex2f(fmaf(x, L2E, negC));
        PUSH(x, tid);
    }

    // process one 2-float4 batch located at p4 (element base via pointer diff)
#define PROCESS(A0, A1)                                                       \
    do {                                                                      \
        float q0 = fmaxf(fmaxf((A0).x, (A0).y), fmaxf((A0).z, (A0).w));       \
        float q1 = fmaxf(fmaxf((A1).x, (A1).y), fmaxf((A1).z, (A1).w));       \
        float imax = fmaxf(q0, q1);                                           \
        if (__any_sync(FULLM, imax > THRESH)) {                               \
            if (imax > THRESH) {                                              \
                int bi0 = pre + 4 * (int)(p4 - p4base);                       \
                int bi1 = bi0 + 4 * THREADS;                                  \
                PUSH((A0).x, bi0 + 0); PUSH((A0).y, bi0 + 1);                 \
                PUSH((A0).z, bi0 + 2); PUSH((A0).w, bi0 + 3);                 \
                PUSH((A1).x, bi1 + 0); PUSH((A1).y, bi1 + 1);                 \
                PUSH((A1).z, bi1 + 2); PUSH((A1).w, bi1 + 3);                 \
            }                                                                 \
        }                                                                     \
        s0 += ex2f(fmaf((A0).x, L2E, negC));                                  \
        s1 += ex2f(fmaf((A0).y, L2E, negC));                                  \
        s0 += ex2f(fmaf((A0).z, L2E, negC));                                  \
        s1 += ex2f(fmaf((A0).w, L2E, negC));                                  \
        s0 += ex2f(fmaf((A1).x, L2E, negC));                                  \
        s1 += ex2f(fmaf((A1).y, L2E, negC));                                  \
        s0 += ex2f(fmaf((A1).z, L2E, negC));                                  \
        s1 += ex2f(fmaf((A1).w, L2E, negC));                                  \
    } while (0)

    // ---- main loop: depth-1 register pipeline (prefetch next while computing) ----
    if (nIter2 > 0) {
        float4 a0 = __ldcs(p4);
        float4 a1 = __ldcs(p4 + THREADS);
        for (int j = nIter2 - 1; j > 0; --j) {
            float4 b0 = __ldcs(p4 + 2 * THREADS);   // prefetch next batch
            float4 b1 = __ldcs(p4 + 3 * THREADS);
            PROCESS(a0, a1);                        // compute current (loads in flight)
            a0 = b0; a1 = b1;
            p4 += 2 * THREADS;
        }
        PROCESS(a0, a1);                            // epilogue batch
    }
#undef PROCESS

    // ---- scalar tail: [pre + vecElems, V) ----
    for (int i = pre + vecElems + tid; i < V; i += THREADS) {
        float x = __ldg(row + i);
        s0 += ex2f(fmaf(x, L2E, negC));
        PUSH(x, i);
    }
#undef PUSH

    // ---- warp reduce s (uniform base for the whole block) ----
    float s = s0 + s1;
#pragma unroll
    for (int off = 16; off; off >>= 1)
        s += __shfl_xor_sync(FULLM, s, off);

    const int lane = tid & 31;
    const int w    = tid >> 5;
    if (lane == 0) s_wS[w] = s;
    __syncthreads();

    // ---- warp 0: top-5 selection + final math ----
    if (w == 0) {
        float tv[TOPK]; int ti[TOPK];
#pragma unroll
        for (int k = 0; k < TOPK; ++k) { tv[k] = NEG_INF; ti[k] = 0; }

        int cnt = s_cnt;
        if (cnt >= TOPK && cnt <= CAP) {
            for (int base = 0; base < cnt; base += 32) {
                int i = base + lane;
                float x = (i < cnt) ? s_vals[i] : NEG_INF;
                int  id = (i < cnt) ? s_idx[i]  : 0;
                unsigned bal = __ballot_sync(FULLM, x > tv[TOPK - 1]);
                while (bal) {
                    int L = __ffs(bal) - 1; bal &= bal - 1;
                    float xv = __shfl_sync(FULLM, x, L);
                    int   iv = __shfl_sync(FULLM, id, L);
                    if (xv > tv[TOPK - 1]) insert5(tv, ti, xv, iv);
                }
            }
        } else {
            // exact fallback (astronomically rare): full-row online top-5
            for (int i0 = 0; i0 < V; i0 += 32) {
                int i = i0 + lane;
                float x = (i < V) ? __ldg(row + i) : NEG_INF;
                unsigned bal = __ballot_sync(FULLM, x > tv[TOPK - 1]);
                while (bal) {
                    int L = __ffs(bal) - 1; bal &= bal - 1;
                    float xv = __shfl_sync(FULLM, x, L);
                    if (xv > tv[TOPK - 1]) insert5(tv, ti, xv, i0 + L);
                }
            }
        }

        if (lane == 0) {
            float sf = 0.0f;
            for (int ww = 0; ww < NWARP; ++ww) sf += s_wS[ww];

            float lse  = (-negC + lg2f(sf)) * LN2;
            int   lab  = __ldg(labels + b);
            float xlab = __ldg(row + lab);
            float nll_cmd = lse - xlab;

#pragma unroll
            for (int c = 0; c < NCAT; ++c) s_cat[c] = 0.0f;
#pragma unroll
            for (int k = 0; k < TOPK; ++k)
                s_cat[s_c2c[ti[k] % ncmd]] += tv[k];

            float mxc = s_cat[0];
#pragma unroll
            for (int c = 1; c < NCAT; ++c) mxc = fmaxf(mxc, s_cat[c]);
            float ssum = 0.0f;
#pragma unroll
            for (int c = 0; c < NCAT; ++c) ssum += ex2f((s_cat[c] - mxc) * L2E);
            int   cl = __ldg(catlab + b);
            float nll_cat = lg2f(ssum) * LN2 + mxc - s_cat[cl];

            g_rowloss[b] = 0.6f * nll_cmd + 0.4f * nll_cat;

            __threadfence();
            unsigned int prev = atomicAdd(&g_done, 1u);
            s_isLast = (prev == (unsigned int)(gridDim.x - 1));
        }
    }
    __syncthreads();

    // ---- fused deterministic final reduction (last block) ----
    if (s_isLast) {
        __threadfence();
        float a = 0.0f;
        for (int i = tid; i < B; i += THREADS) a += g_rowloss[i];
        s_red[tid] = a;
        __syncthreads();
#pragma unroll
        for (int off = THREADS / 2; off; off >>= 1) {
            if (tid < off) s_red[tid] += s_red[tid + off];
            __syncthreads();
        }
        if (tid == 0) {
            out[0] = s_red[0] * (1.0f / (float)B);
            atomicExch(&g_done, 0u);
        }
    }
}

extern "C" void kernel_launch(void* const* d_in, const int* in_sizes, int n_in,
                              void* d_out, int out_size)
{
    const float* logits = (const float*)d_in[0];
    const int*   labels = (const int*)d_in[1];
    const int*   catlab = (const int*)d_in[2];
    const int*   c2c    = (const int*)d_in[3];

    const int B    = in_sizes[1];
    const int V    = in_sizes[0] / B;
    const int ncmd = in_sizes[3];

    hier_loss_fused<<<B, THREADS>>>(logits, labels, catlab, c2c,
                                    (float*)d_out, V, ncmd, B);
}

// round 12
// speedup vs baseline: 1.0294x; 1.0294x over previous
#include <cuda_runtime.h>
#include <cstdint>

#define THREADS 256
#define NWARP (THREADS / 32)
#define TOPK 5
#define NCAT 8
#define CAP 256
#define NSTAGE 3
#define CHUNK_F4 512                    /* 512 float4 = 8 KB per chunk */
#define CHUNK_BYTES (CHUNK_F4 * 16)
#define FULLM 0xffffffffu
#define L2E 1.4426950408889634f
#define LN2 0.6931471805599453f
#define NEG_INF (-__int_as_float(0x7f800000))
#define THRESH 3.25f

__device__ float g_rowloss[8192];
__device__ unsigned int g_done = 0;

__device__ __forceinline__ float ex2f(float x) {
    float y; asm("ex2.approx.ftz.f32 %0, %1;" : "=f"(y) : "f"(x)); return y;
}
__device__ __forceinline__ float lg2f(float x) {
    float y; asm("lg2.approx.ftz.f32 %0, %1;" : "=f"(y) : "f"(x)); return y;
}
__device__ __forceinline__ uint32_t smem_u32(const void* p) {
    uint32_t a;
    asm("{ .reg .u64 t; cvta.to.shared.u64 t, %1; cvt.u32.u64 %0, t; }"
        : "=r"(a) : "l"(p));
    return a;
}
__device__ __forceinline__ void mbar_init(uint32_t mbar, uint32_t cnt) {
    asm volatile("mbarrier.init.shared.b64 [%0], %1;" :: "r"(mbar), "r"(cnt) : "memory");
}
__device__ __forceinline__ void mbar_expect_tx(uint32_t mbar, uint32_t bytes) {
    asm volatile("mbarrier.arrive.expect_tx.shared.b64 _, [%0], %1;"
                 :: "r"(mbar), "r"(bytes) : "memory");
}
__device__ __forceinline__ void mbar_wait(uint32_t mbar, uint32_t phase) {
    asm volatile(
        "{\n\t.reg .pred P;\n\t"
        "W_%=:\n\t"
        "mbarrier.try_wait.parity.acquire.cta.shared::cta.b64 P, [%0], %1, 0x989680;\n\t"
        "@!P bra W_%=;\n\t"
        "}" :: "r"(mbar), "r"(phase) : "memory");
}
__device__ __forceinline__ void bulk_ld(uint32_t dst, const void* src,
                                        uint32_t bytes, uint32_t mbar) {
    asm volatile(
        "cp.async.bulk.shared::cta.global.mbarrier::complete_tx::bytes [%0], [%1], %2, [%3];"
        :: "r"(dst), "l"(src), "r"(bytes), "r"(mbar) : "memory");
}

__device__ __forceinline__ void insert5(float (&tv)[TOPK], int (&ti)[TOPK], float v, int idx) {
    tv[TOPK - 1] = v; ti[TOPK - 1] = idx;
#pragma unroll
    for (int k = TOPK - 1; k > 0; --k) {
        if (tv[k] > tv[k - 1]) {
            float tf = tv[k]; tv[k] = tv[k - 1]; tv[k - 1] = tf;
            int   tt = ti[k]; ti[k] = ti[k - 1]; ti[k - 1] = tt;
        }
    }
}

__global__ void __launch_bounds__(THREADS, 8)
hier_loss_fused(const float* __restrict__ logits,
                const int* __restrict__ labels,
                const int* __restrict__ catlab,
                const int* __restrict__ c2c,
                float* __restrict__ out,
                int V, int ncmd, int B)
{
    const int b   = blockIdx.x;
    const int tid = threadIdx.x;
    const float* row = logits + (size_t)b * (size_t)V;

    __shared__ __align__(128) float4 s_stage[NSTAGE][CHUNK_F4];
    __shared__ __align__(8) unsigned long long s_mbar[NSTAGE];
    __shared__ int   s_c2c[64];
    __shared__ float s_wS[NWARP];
    __shared__ float s_vals[CAP];           /* reused as reduction buffer */
    __shared__ int   s_idx[CAP];
    __shared__ int   s_cnt;
    __shared__ float s_cat[NCAT];
    __shared__ int   s_isLast;

    if (tid < 64 && tid < ncmd) s_c2c[tid] = c2c[tid];
    if (tid == 0) {
        s_cnt = 0;
#pragma unroll
        for (int st = 0; st < NSTAGE; ++st)
            mbar_init(smem_u32(&s_mbar[st]), 1u);
    }
    __syncthreads();

    const float negC = -__ldg(row) * L2E;       // block-wide base (log2 domain)
    float s0 = 0.f, s1 = 0.f;

    const int mis = (int)(((size_t)b * (size_t)V) & 3);
    const int pre = (4 - mis) & 3;
    const int nv4 = (V - pre) >> 2;             // aligned float4 count (TMA region)
    const int nchunks = (nv4 + CHUNK_F4 - 1) / CHUNK_F4;
    const float4* __restrict__ p4base = (const float4*)(row + pre);

#define PUSH(val, ei)                                                         \
    do {                                                                      \
        if ((val) > THRESH) {                                                 \
            int pos = atomicAdd(&s_cnt, 1);                                   \
            if (pos < CAP) { s_vals[pos] = (val); s_idx[pos] = (ei); }        \
        }                                                                     \
    } while (0)

    // ---- head (pre <= 3 elements, predicated, no ballot) ----
    if (tid < pre) {
        float x = __ldg(row + tid);
        s0 += ex2f(fmaf(x, L2E, negC));
        PUSH(x, tid);
    }

    // ---- producer prologue: fill the ring ----
    if (tid == 0) {
        int npro = nchunks < NSTAGE ? nchunks : NSTAGE;
        for (int c = 0; c < npro; ++c) {
            int fb = c * CHUNK_F4;
            int n4 = nv4 - fb; if (n4 > CHUNK_F4) n4 = CHUNK_F4;
            uint32_t bytes = (uint32_t)n4 * 16u;
            uint32_t mb = smem_u32(&s_mbar[c]);
            mbar_expect_tx(mb, bytes);
            bulk_ld(smem_u32(&s_stage[c][0]), p4base + fb, bytes, mb);
        }
    }

    // ---- main pipeline loop ----
    int stg = 0, ph = 0;
    for (int c = 0; c < nchunks; ++c) {
        mbar_wait(smem_u32(&s_mbar[stg]), (uint32_t)ph);

        const int fb = c * CHUNK_F4;
        int n4 = nv4 - fb; if (n4 > CHUNK_F4) n4 = CHUNK_F4;
        const float4* st = s_stage[stg];

        if (n4 == CHUNK_F4) {
            // full chunk: 2 x LDS.128 per thread, one ballot per 256-elem window
            float4 a0 = st[tid];
            float4 a1 = st[tid + THREADS];

            float imax = fmaxf(
                fmaxf(fmaxf(a0.x, a0.y), fmaxf(a0.z, a0.w)),
                fmaxf(fmaxf(a1.x, a1.y), fmaxf(a1.z, a1.w)));
            if (__any_sync(FULLM, imax > THRESH)) {
                if (imax > THRESH) {
                    int bi0 = pre + 4 * (fb + tid);
                    int bi1 = pre + 4 * (fb + tid + THREADS);
                    PUSH(a0.x, bi0 + 0); PUSH(a0.y, bi0 + 1);
                    PUSH(a0.z, bi0 + 2); PUSH(a0.w, bi0 + 3);
                    PUSH(a1.x, bi1 + 0); PUSH(a1.y, bi1 + 1);
                    PUSH(a1.z, bi1 + 2); PUSH(a1.w, bi1 + 3);
                }
            }

            s0 += ex2f(fmaf(a0.x, L2E, negC));
            s1 += ex2f(fmaf(a0.y, L2E, negC));
            s0 += ex2f(fmaf(a0.z, L2E, negC));
            s1 += ex2f(fmaf(a0.w, L2E, negC));
            s0 += ex2f(fmaf(a1.x, L2E, negC));
            s1 += ex2f(fmaf(a1.y, L2E, negC));
            s0 += ex2f(fmaf(a1.z, L2E, negC));
            s1 += ex2f(fmaf(a1.w, L2E, negC));
        } else {
            // remainder chunk (once per row): ballot-free predicated pushes
            for (int f4 = tid; f4 < n4; f4 += THREADS) {
                float4 a = st[f4];
                int bi = pre + 4 * (fb + f4);
                s0 += ex2f(fmaf(a.x, L2E, negC));
                s1 += ex2f(fmaf(a.y, L2E, negC));
                s0 += ex2f(fmaf(a.z, L2E, negC));
                s1 += ex2f(fmaf(a.w, L2E, negC));
                PUSH(a.x, bi + 0); PUSH(a.y, bi + 1);
                PUSH(a.z, bi + 2); PUSH(a.w, bi + 3);
            }
        }

        __syncthreads();                        // all reads of this stage done

        int nc = c + NSTAGE;
        if (tid == 0 && nc < nchunks) {
            int fb2 = nc * CHUNK_F4;
            int n42 = nv4 - fb2; if (n42 > CHUNK_F4) n42 = CHUNK_F4;
            uint32_t bytes = (uint32_t)n42 * 16u;
            uint32_t mb = smem_u32(&s_mbar[stg]);
            mbar_expect_tx(mb, bytes);
            bulk_ld(smem_u32(&s_stage[stg][0]), p4base + fb2, bytes, mb);
        }

        if (++stg == NSTAGE) { stg = 0; ph ^= 1; }
    }

    // ---- tail (<= 3 elements past the float4 region) ----
    for (int i = pre + nv4 * 4 + tid; i < V; i += THREADS) {
        float x = __ldg(row + i);
        s0 += ex2f(fmaf(x, L2E, negC));
        PUSH(x, i);
    }
#undef PUSH

    // ---- warp reduce s (uniform base for the whole block) ----
    float s = s0 + s1;
#pragma unroll
    for (int off = 16; off; off >>= 1)
        s += __shfl_xor_sync(FULLM, s, off);

    const int lane = tid & 31;
    const int w    = tid >> 5;
    if (lane == 0) s_wS[w] = s;
    __syncthreads();

    // ---- warp 0: top-5 selection + final math ----
    if (w == 0) {
        float tv[TOPK]; int ti[TOPK];
#pragma unroll
        for (int k = 0; k < TOPK; ++k) { tv[k] = NEG_INF; ti[k] = 0; }

        int cnt = s_cnt;
        if (cnt >= TOPK && cnt <= CAP) {
            for (int base = 0; base < cnt; base += 32) {
                int i = base + lane;
                float x = (i < cnt) ? s_vals[i] : NEG_INF;
                int  id = (i < cnt) ? s_idx[i]  : 0;
                unsigned bal = __ballot_sync(FULLM, x > tv[TOPK - 1]);
                while (bal) {
                    int L = __ffs(bal) - 1; bal &= bal - 1;
                    float xv = __shfl_sync(FULLM, x, L);
                    int   iv = __shfl_sync(FULLM, id, L);
                    if (xv > tv[TOPK - 1]) insert5(tv, ti, xv, iv);
                }
            }
        } else {
            // exact fallback (astronomically rare): full-row online top-5
            for (int i0 = 0; i0 < V; i0 += 32) {
                int i = i0 + lane;
                float x = (i < V) ? __ldg(row + i) : NEG_INF;
                unsigned bal = __ballot_sync(FULLM, x > tv[TOPK - 1]);
                while (bal) {
                    int L = __ffs(bal) - 1; bal &= bal - 1;
                    float xv = __shfl_sync(FULLM, x, L);
                    if (xv > tv[TOPK - 1]) insert5(tv, ti, xv, i0 + L);
                }
            }
        }

        if (lane == 0) {
            float sf = 0.0f;
            for (int ww = 0; ww < NWARP; ++ww) sf += s_wS[ww];

            float lse  = (-negC + lg2f(sf)) * LN2;
            int   lab  = __ldg(labels + b);
            float xlab = __ldg(row + lab);
            float nll_cmd = lse - xlab;

#pragma unroll
            for (int c = 0; c < NCAT; ++c) s_cat[c] = 0.0f;
#pragma unroll
            for (int k = 0; k < TOPK; ++k)
                s_cat[s_c2c[ti[k] % ncmd]] += tv[k];

            float mxc = s_cat[0];
#pragma unroll
            for (int c = 1; c < NCAT; ++c) mxc = fmaxf(mxc, s_cat[c]);
            float ssum = 0.0f;
#pragma unroll
            for (int c = 0; c < NCAT; ++c) ssum += ex2f((s_cat[c] - mxc) * L2E);
            int   cl = __ldg(catlab + b);
            float nll_cat = lg2f(ssum) * LN2 + mxc - s_cat[cl];

            g_rowloss[b] = 0.6f * nll_cmd + 0.4f * nll_cat;

            __threadfence();
            unsigned int prev = atomicAdd(&g_done, 1u);
            s_isLast = (prev == (unsigned int)(gridDim.x - 1));
        }
    }
    __syncthreads();

    // ---- fused deterministic final reduction (last block) ----
    if (s_isLast) {
        __threadfence();
        float a = 0.0f;
        for (int i = tid; i < B; i += THREADS) a += g_rowloss[i];
        s_vals[tid] = a;                        /* CAP == THREADS */
        __syncthreads();
#pragma unroll
        for (int off = THREADS / 2; off; off >>= 1) {
            if (tid < off) s_vals[tid] += s_vals[tid + off];
            __syncthreads();
        }
        if (tid == 0) {
            out[0] = s_vals[0] * (1.0f / (float)B);
            atomicExch(&g_done, 0u);
        }
    }
}

extern "C" void kernel_launch(void* const* d_in, const int* in_sizes, int n_in,
                              void* d_out, int out_size)
{
    const float* logits = (const float*)d_in[0];
    const int*   labels = (const int*)d_in[1];
    const int*   catlab = (const int*)d_in[2];
    const int*   c2c    = (const int*)d_in[3];

    const int B    = in_sizes[1];
    const int V    = in_sizes[0] / B;
    const int ncmd = in_sizes[3];

    hier_loss_fused<<<B, THREADS>>>(logits, labels, catlab, c2c,
                                    (float*)d_out, V, ncmd, B);
}